// round 2
// baseline (speedup 1.0000x reference)
#include <cuda_runtime.h>
#include <math.h>

// Problem constants
#define Bb   16
#define CIN  64
#define Hh   160
#define Ww   192
#define Nn   1000
#define AFC  16
#define Ss   96
#define Dd   2560          // AFC * H
#define HW   30720         // H * W
#define NCOLS 293          // NC + 3 + 3S  (also anchors row length)

// Output layout: reg_proposals | attn_mat | feats (tuple flattened in order)
#define OUT_REG_ELEMS  ((size_t)Bb * Nn * NCOLS)        // 4,688,000
#define OUT_ATTN_ELEMS ((size_t)Bb * Nn * Nn)           // 16,000,000
#define OUT_FEATS_ELEMS ((size_t)Bb * AFC * HW)         // 7,864,320

// ---------------- scratch (device globals: no runtime allocation) ----------
__device__ float g_baf[(size_t)Bb * Nn * Dd];     // 164 MB
__device__ float g_att[(size_t)Bb * Nn * Dd];     // 164 MB
__device__ float g_scores[(size_t)Bb * Nn * 1000];// 64 MB (ld=1000, 999 valid)

// ---------------------------------------------------------------------------
// Kernel 1: 1x1 conv  feats[b,o,h,w] = sum_c x[b,c,h,w]*w[o,c] + bias[o]
// ---------------------------------------------------------------------------
__global__ __launch_bounds__(256)
void conv_kernel(const float* __restrict__ x, const float* __restrict__ w,
                 const float* __restrict__ bias, float* __restrict__ feats) {
    __shared__ float ws[AFC * CIN];
    __shared__ float bs[AFC];
    int tid = threadIdx.x;
    for (int t = tid; t < AFC * CIN; t += 256) ws[t] = w[t];
    if (tid < AFC) bs[tid] = bias[tid];
    __syncthreads();

    unsigned idx = blockIdx.x * 256u + tid;
    if (idx >= (unsigned)(Bb * (HW / 4))) return;
    int b = idx / (HW / 4);
    int q = idx % (HW / 4);
    size_t hw = (size_t)q * 4;

    const float* xp = x + (size_t)b * CIN * HW + hw;
    float4 acc[AFC];
#pragma unroll
    for (int o = 0; o < AFC; ++o) {
        float bv = bs[o];
        acc[o] = make_float4(bv, bv, bv, bv);
    }
#pragma unroll 4
    for (int c = 0; c < CIN; ++c) {
        float4 xv = *(const float4*)(xp + (size_t)c * HW);
#pragma unroll
        for (int o = 0; o < AFC; ++o) {
            float wv = ws[o * CIN + c];
            acc[o].x += xv.x * wv;
            acc[o].y += xv.y * wv;
            acc[o].z += xv.z * wv;
            acc[o].w += xv.w * wv;
        }
    }
    float* fp = feats + (size_t)b * AFC * HW + hw;
#pragma unroll
    for (int o = 0; o < AFC; ++o)
        *(float4*)(fp + (size_t)o * HW) = acc[o];
}

// ---------------------------------------------------------------------------
// Kernel 2: ROI gather  baf[b,n, a*H+h] = invalid[n,h] ? 0 : feats[b,a,h,cut_xs[n,h]]
// invalid_mask is a 4-byte dtype (int32 or float32) — test the raw word != 0.
// ---------------------------------------------------------------------------
__global__ __launch_bounds__(256)
void gather_kernel(const float* __restrict__ feats, const int* __restrict__ cut_xs,
                   const unsigned* __restrict__ invalid, float* __restrict__ baf) {
    unsigned idx = blockIdx.x * 256u + threadIdx.x;   // total = 40,960,000 exactly
    int h = idx % Hh;
    unsigned r = idx / Hh;
    int a = r % AFC; r /= AFC;
    int n = r % Nn;
    int b = r / Nn;
    int xi = cut_xs[n * Hh + h];
    float v = 0.0f;
    if (invalid[n * Hh + h] == 0u)
        v = feats[(((size_t)b * AFC + a) * Hh + h) * Ww + xi];
    baf[(size_t)idx] = v;
}

// ---------------------------------------------------------------------------
// Generic fp32 tiled GEMM: C = Aop * Bop
//   A: row-major M x K, optionally split at KA1 (A1 covers k<KA1, A2 the rest,
//      both with row stride lda).
//   BMODE 0 (TN): B row-major N x K (rows split at NB1 between B1/B2, stride ldb)
//   BMODE 1 (NN): B row-major K x N (B1 only, stride ldb)
//   EPI 0: C[m,n] = acc + bias1[n]                       (scores)
//   EPI 1: C[m,n] = acc                                  (att_feats)
//   EPI 2: fused reg+cls epilogue into reg_proposals rows (ldc = 293)
// Tiles: 128x128x8, 256 threads, 8x8 per thread.
// ---------------------------------------------------------------------------
#define BM 128
#define BN 128
#define BK 8

template<int BMODE, int EPI>
__global__ __launch_bounds__(256)
void gemm_kernel(const float* __restrict__ A1, const float* __restrict__ A2, int KA1,
                 const float* __restrict__ B1, const float* __restrict__ B2, int NB1,
                 const float* __restrict__ bias1, const float* __restrict__ bias2,
                 const float* __restrict__ anchors,
                 float* __restrict__ C,
                 int M, int N, int K, int lda, int ldb, int ldc,
                 size_t sA, size_t sB, size_t sC) {
    __shared__ float As[BK][BM + 4];
    __shared__ float Bs[BK][BN + 4];

    A1 += sA * blockIdx.z;
    A2 += sA * blockIdx.z;
    B1 += sB * blockIdx.z;
    C  += sC * blockIdx.z;

    int tid = threadIdx.x;
    int bm = blockIdx.y * BM;
    int bn = blockIdx.x * BN;
    int tx = tid & 15;        // 0..15  -> 8 cols each
    int ty = tid >> 4;        // 0..15  -> 8 rows each

    int l_r = tid >> 1;              // 0..127
    int l_c = (tid & 1) * 4;         // 0 or 4

    float acc[8][8];
#pragma unroll
    for (int i = 0; i < 8; ++i)
#pragma unroll
        for (int j = 0; j < 8; ++j) acc[i][j] = 0.0f;

    for (int k0 = 0; k0 < K; k0 += BK) {
        // ---- load A tile (transpose into As[k][m]) ----
        {
            int gr = bm + l_r;
            float4 v = make_float4(0.f, 0.f, 0.f, 0.f);
            if (gr < M) {
                const float* src = (k0 < KA1)
                    ? (A1 + (size_t)gr * lda + k0 + l_c)
                    : (A2 + (size_t)gr * lda + (k0 - KA1) + l_c);
                v = *(const float4*)src;
            }
            As[l_c + 0][l_r] = v.x;
            As[l_c + 1][l_r] = v.y;
            As[l_c + 2][l_r] = v.z;
            As[l_c + 3][l_r] = v.w;
        }
        // ---- load B tile ----
        if (BMODE == 0) { // TN: B is N x K
            int gn = bn + l_r;
            float4 v = make_float4(0.f, 0.f, 0.f, 0.f);
            if (gn < N) {
                const float* src = (gn < NB1)
                    ? (B1 + (size_t)gn * ldb + k0 + l_c)
                    : (B2 + (size_t)(gn - NB1) * ldb + k0 + l_c);
                v = *(const float4*)src;
            }
            Bs[l_c + 0][l_r] = v.x;
            Bs[l_c + 1][l_r] = v.y;
            Bs[l_c + 2][l_r] = v.z;
            Bs[l_c + 3][l_r] = v.w;
        } else {          // NN: B is K x N
            int kk = tid >> 5;             // 0..7
            int nq = (tid & 31) * 4;       // 0..124
            int gn = bn + nq;
            float4 v = make_float4(0.f, 0.f, 0.f, 0.f);
            if (gn < N)
                v = *(const float4*)(B1 + (size_t)(k0 + kk) * ldb + gn);
            Bs[kk][nq + 0] = v.x;
            Bs[kk][nq + 1] = v.y;
            Bs[kk][nq + 2] = v.z;
            Bs[kk][nq + 3] = v.w;
        }
        __syncthreads();

#pragma unroll
        for (int k = 0; k < BK; ++k) {
            float a[8], b[8];
            float4 a0 = *(const float4*)&As[k][ty * 8];
            float4 a1 = *(const float4*)&As[k][ty * 8 + 4];
            float4 b0 = *(const float4*)&Bs[k][tx * 8];
            float4 b1 = *(const float4*)&Bs[k][tx * 8 + 4];
            a[0]=a0.x; a[1]=a0.y; a[2]=a0.z; a[3]=a0.w;
            a[4]=a1.x; a[5]=a1.y; a[6]=a1.z; a[7]=a1.w;
            b[0]=b0.x; b[1]=b0.y; b[2]=b0.z; b[3]=b0.w;
            b[4]=b1.x; b[5]=b1.y; b[6]=b1.z; b[7]=b1.w;
#pragma unroll
            for (int i = 0; i < 8; ++i)
#pragma unroll
                for (int j = 0; j < 8; ++j)
                    acc[i][j] += a[i] * b[j];
        }
        __syncthreads();
    }

    // ---- epilogue ----
#pragma unroll
    for (int i = 0; i < 8; ++i) {
        int m = bm + ty * 8 + i;
        if (m >= M) continue;
        int nidx = m % Nn;  // only used by EPI 2
#pragma unroll
        for (int j = 0; j < 8; ++j) {
            int n = bn + tx * 8 + j;
            if (n >= N) continue;
            float v = acc[i][j];
            if (EPI == 0) {
                C[(size_t)m * ldc + n] = v + bias1[n];
            } else if (EPI == 1) {
                C[(size_t)m * ldc + n] = v;
            } else { // EPI == 2: fused reg (n<288) + cls (n>=288)
                if (n < NB1) {
                    v += bias1[n];
                    if (n >= 2 * Ss) v = 1.0f / (1.0f + expf(-v));
                    v += anchors[(size_t)nidx * NCOLS + 5 + n];
                    C[(size_t)m * ldc + 5 + n] = v;
                } else {
                    v += bias2[n - NB1];
                    C[(size_t)m * ldc + (n - NB1)] = v;
                }
            }
        }
    }
}

// ---------------------------------------------------------------------------
// Kernel: softmax over 999 scores per row, scattered into attn_mat row of 1000
// with a zero inserted at the diagonal position i.
// ---------------------------------------------------------------------------
__global__ __launch_bounds__(256)
void softmax_kernel(const float* __restrict__ scores, float* __restrict__ attn_out) {
    __shared__ float red[256];
    int m = blockIdx.x;            // b*1000 + i
    int i = m % Nn;
    int t = threadIdx.x;
    const float* row = scores + (size_t)m * 1000;

    float v[4];
    float mx = -INFINITY;
#pragma unroll
    for (int r = 0; r < 4; ++r) {
        int j = t + r * 256;
        v[r] = (j < Nn - 1) ? row[j] : -INFINITY;
        mx = fmaxf(mx, v[r]);
    }
    red[t] = mx;
    __syncthreads();
    for (int s = 128; s > 0; s >>= 1) {
        if (t < s) red[t] = fmaxf(red[t], red[t + s]);
        __syncthreads();
    }
    mx = red[0];
    __syncthreads();

    float sum = 0.0f;
#pragma unroll
    for (int r = 0; r < 4; ++r) {
        int j = t + r * 256;
        v[r] = (j < Nn - 1) ? __expf(v[r] - mx) : 0.0f;
        sum += v[r];
    }
    red[t] = sum;
    __syncthreads();
    for (int s = 128; s > 0; s >>= 1) {
        if (t < s) red[t] += red[t + s];
        __syncthreads();
    }
    float inv = 1.0f / red[0];

    float* out = attn_out + (size_t)m * Nn;
#pragma unroll
    for (int r = 0; r < 4; ++r) {
        int j = t + r * 256;
        if (j < Nn - 1) {
            int pos = j + (j >= i);
            out[pos] = v[r] * inv;
        }
    }
    if (t == 0) out[i] = 0.0f;
}

// ---------------------------------------------------------------------------
// Kernel: copy anchors[:, 2:5] into reg_proposals[:, :, 2:5]
// ---------------------------------------------------------------------------
__global__ void anchor_kernel(const float* __restrict__ anchors, float* __restrict__ out) {
    int idx = blockIdx.x * blockDim.x + threadIdx.x;
    if (idx >= Bb * Nn * 3) return;
    int m = idx / 3, t = idx % 3;
    out[(size_t)m * NCOLS + 2 + t] = anchors[(size_t)(m % Nn) * NCOLS + 2 + t];
}

// ---------------------------------------------------------------------------
extern "C" void kernel_launch(void* const* d_in, const int* in_sizes, int n_in,
                              void* d_out, int out_size) {
    const float*    x       = (const float*)d_in[0];   // batch_features
    const float*    conv_w  = (const float*)d_in[1];
    const float*    conv_b  = (const float*)d_in[2];
    const int*      cut_xs  = (const int*)d_in[3];
    const unsigned* invalid = (const unsigned*)d_in[4]; // bool mask widened to 4-byte dtype
    const float*    anchors = (const float*)d_in[5];
    const float*    attn_w  = (const float*)d_in[6];
    const float*    attn_b  = (const float*)d_in[7];
    const float*    cls_w   = (const float*)d_in[8];
    const float*    cls_b   = (const float*)d_in[9];
    const float*    reg_w   = (const float*)d_in[10];
    const float*    reg_b   = (const float*)d_in[11];

    float* out       = (float*)d_out;
    float* out_reg   = out;
    float* out_attn  = out + OUT_REG_ELEMS;
    float* out_feats = out_attn + OUT_ATTN_ELEMS;

    float *baf, *att, *scores;
    cudaGetSymbolAddress((void**)&baf, g_baf);
    cudaGetSymbolAddress((void**)&att, g_att);
    cudaGetSymbolAddress((void**)&scores, g_scores);

    // 1) 1x1 conv -> feats (directly into d_out)
    conv_kernel<<<480, 256>>>(x, conv_w, conv_b, out_feats);

    // 2) ROI gather -> baf
    gather_kernel<<<160000, 256>>>(out_feats, cut_xs, invalid, baf);

    // 3) scores = baf @ attn_w^T + attn_b   (TN, M=16000 N=999 K=2560)
    gemm_kernel<0, 0><<<dim3(8, 125, 1), 256>>>(
        baf, baf, Dd, attn_w, attn_w, Nn - 1, attn_b, attn_b, nullptr,
        scores, Bb * Nn, Nn - 1, Dd, Dd, Dd, 1000, 0, 0, 0);

    // 4) softmax + diagonal-zero scatter -> attn_mat (in d_out)
    softmax_kernel<<<Bb * Nn, 256>>>(scores, out_attn);

    // 5) att_feats = attn_mat @ baf  (NN batched, per-b M=1000 N=2560 K=1000)
    gemm_kernel<1, 1><<<dim3(20, 8, Bb), 256>>>(
        out_attn, out_attn, Nn, baf, baf, Dd + 1, nullptr, nullptr, nullptr,
        att, Nn, Dd, Nn, Nn, Dd, Dd,
        (size_t)Nn * Nn, (size_t)Nn * Dd, (size_t)Nn * Dd);

    // 6) fused reg+cls GEMM over concat A = [att | baf] (TN, M=16000 N=290 K=5120)
    gemm_kernel<0, 2><<<dim3(3, 125, 1), 256>>>(
        att, baf, Dd, reg_w, cls_w, 3 * Ss, reg_b, cls_b, anchors,
        out_reg, Bb * Nn, 3 * Ss + 2, 2 * Dd, Dd, 2 * Dd, NCOLS, 0, 0, 0);

    // 7) anchors[:, 2:5] passthrough columns
    anchor_kernel<<<(Bb * Nn * 3 + 255) / 256, 256>>>(anchors, out_reg);
}

// round 4
// speedup vs baseline: 2.1870x; 2.1870x over previous
#include <cuda_runtime.h>
#include <math.h>
#include <stdint.h>

// Problem constants
#define Bb   16
#define CIN  64
#define Hh   160
#define Ww   192
#define Nn   1000
#define AFC  16
#define Ss   96
#define Dd   2560          // AFC * H
#define HW   30720         // H * W
#define NCOLS 293

#define OUT_REG_ELEMS  ((size_t)Bb * Nn * NCOLS)
#define OUT_ATTN_ELEMS ((size_t)Bb * Nn * Nn)

// ---------------- scratch ----------------
__device__ float g_baf[(size_t)Bb * Nn * Dd];      // 164 MB
__device__ float g_bafT[(size_t)Bb * Nn * Dd];     // 164 MB ([D][N] per batch)
__device__ float g_att[(size_t)Bb * Nn * Dd];      // 164 MB
__device__ float g_scores[(size_t)Bb * Nn * 1000]; // 64 MB

// =============================== conv ======================================
__global__ __launch_bounds__(256)
void conv_kernel(const float* __restrict__ x, const float* __restrict__ w,
                 const float* __restrict__ bias, float* __restrict__ feats) {
    __shared__ float ws[AFC * CIN];
    __shared__ float bs[AFC];
    int tid = threadIdx.x;
    for (int t = tid; t < AFC * CIN; t += 256) ws[t] = w[t];
    if (tid < AFC) bs[tid] = bias[tid];
    __syncthreads();

    unsigned idx = blockIdx.x * 256u + tid;
    if (idx >= (unsigned)(Bb * (HW / 4))) return;
    int b = idx / (HW / 4);
    int q = idx % (HW / 4);
    size_t hw = (size_t)q * 4;

    const float* xp = x + (size_t)b * CIN * HW + hw;
    float4 acc[AFC];
#pragma unroll
    for (int o = 0; o < AFC; ++o) {
        float bv = bs[o];
        acc[o] = make_float4(bv, bv, bv, bv);
    }
#pragma unroll 4
    for (int c = 0; c < CIN; ++c) {
        float4 xv = *(const float4*)(xp + (size_t)c * HW);
#pragma unroll
        for (int o = 0; o < AFC; ++o) {
            float wv = ws[o * CIN + c];
            acc[o].x += xv.x * wv; acc[o].y += xv.y * wv;
            acc[o].z += xv.z * wv; acc[o].w += xv.w * wv;
        }
    }
    float* fp = feats + (size_t)b * AFC * HW + hw;
#pragma unroll
    for (int o = 0; o < AFC; ++o)
        *(float4*)(fp + (size_t)o * HW) = acc[o];
}

// =============================== gather ====================================
__global__ __launch_bounds__(256)
void gather_kernel(const float* __restrict__ feats, const int* __restrict__ cut_xs,
                   const unsigned* __restrict__ invalid, float* __restrict__ baf) {
    unsigned idx = blockIdx.x * 256u + threadIdx.x;   // 40,960,000 exactly
    int h = idx % Hh;
    unsigned r = idx / Hh;
    int a = r % AFC; r /= AFC;
    int n = r % Nn;
    int b = r / Nn;
    int xi = cut_xs[n * Hh + h];
    float v = 0.0f;
    if (invalid[n * Hh + h] == 0u)
        v = feats[(((size_t)b * AFC + a) * Hh + h) * Ww + xi];
    baf[(size_t)idx] = v;
}

// ============================ transpose baf -> bafT =========================
__global__ __launch_bounds__(256)
void transpose_kernel(const float* __restrict__ src, float* __restrict__ dst) {
    __shared__ float tile[32][33];
    int b = blockIdx.z;
    int n0 = blockIdx.y * 32, d0 = blockIdx.x * 32;
    const float* s = src + (size_t)b * Nn * Dd;
    float* dt = dst + (size_t)b * Nn * Dd;
    int tx = threadIdx.x, ty = threadIdx.y;  // 32 x 8
#pragma unroll
    for (int r = ty; r < 32; r += 8) {
        int n = n0 + r;
        tile[r][tx] = (n < Nn) ? s[(size_t)n * Dd + d0 + tx] : 0.0f;
    }
    __syncthreads();
#pragma unroll
    for (int r = ty; r < 32; r += 8) {
        int n = n0 + tx;
        if (n < Nn) dt[(size_t)(d0 + r) * Nn + n] = tile[tx][r];
    }
}

// ====================== tf32 warp-MMA GEMM (TN) =============================
// C[M,N] = A[M,K] * B[N,K]^T  via mma.sync.m16n8k8.tf32 (sm_80+, compute_100 OK)
// A split at KA1 (A1 | A2, row stride lda). B rows split at NB1 (B1 | B2, ldb).
// EPI 0: C = acc + bias1[n]. EPI 1: plain. EPI 2: fused reg/cls (ldc=293).
#define GBM 128
#define GBN 128
#define GBK 16
#define SAS (GBM + 8)
#define SBS (GBN + 8)

__device__ __forceinline__ uint32_t f2tf(float f) {
    uint32_t u;
    asm("cvt.rna.tf32.f32 %0, %1;" : "=r"(u) : "f"(f));
    return u;
}
__device__ __forceinline__ void mma_tf32(float* d, const uint32_t* a, const uint32_t* b) {
    asm volatile(
        "mma.sync.aligned.m16n8k8.row.col.f32.tf32.tf32.f32 "
        "{%0,%1,%2,%3}, {%4,%5,%6,%7}, {%8,%9}, {%0,%1,%2,%3};"
        : "+f"(d[0]), "+f"(d[1]), "+f"(d[2]), "+f"(d[3])
        : "r"(a[0]), "r"(a[1]), "r"(a[2]), "r"(a[3]), "r"(b[0]), "r"(b[1]));
}

__device__ __forceinline__ float4 ldA(const float* A1, const float* A2, int KA1, int lda,
                                      int M, int K, int bm, int linear, int k0) {
    int r = linear >> 2, c4 = linear & 3;
    int gr = bm + r, k = k0 + c4 * 4;
    float4 v = make_float4(0.f, 0.f, 0.f, 0.f);
    if (gr < M && k < K) {
        const float* s = (k < KA1) ? A1 + (size_t)gr * lda + k
                                   : A2 + (size_t)gr * lda + (k - KA1);
        v = *(const float4*)s;
    }
    return v;
}
__device__ __forceinline__ float4 ldB(const float* B1, const float* B2, int NB1, int ldb,
                                      int N, int K, int bn, int linear, int k0) {
    int r = linear >> 2, c4 = linear & 3;
    int gn = bn + r, k = k0 + c4 * 4;
    float4 v = make_float4(0.f, 0.f, 0.f, 0.f);
    if (gn < N && k < K) {
        const float* s = (gn < NB1) ? B1 + (size_t)gn * ldb + k
                                    : B2 + (size_t)(gn - NB1) * ldb + k;
        v = *(const float4*)s;
    }
    return v;
}

template<int EPI>
__device__ __forceinline__ void epi_store(float* __restrict__ C, int ldc, int M, int N,
                                          const float* __restrict__ bias1,
                                          const float* __restrict__ bias2,
                                          const float* __restrict__ anchors,
                                          int m, int n, float v) {
    if (m >= M || n >= N) return;
    if (EPI == 0) {
        C[(size_t)m * ldc + n] = v + bias1[n];
    } else if (EPI == 1) {
        C[(size_t)m * ldc + n] = v;
    } else {
        int nidx = m % Nn;
        if (n < 288) {
            v += bias1[n];
            if (n >= 192) v = 1.0f / (1.0f + expf(-v));
            v += anchors[(size_t)nidx * NCOLS + 5 + n];
            C[(size_t)m * ldc + 5 + n] = v;
        } else {
            C[(size_t)m * ldc + (n - 288)] = v + bias2[n - 288];
        }
    }
}

template<int EPI>
__global__ __launch_bounds__(256)
void mma_gemm(const float* __restrict__ A1, const float* __restrict__ A2, int KA1, int lda,
              const float* __restrict__ B1, const float* __restrict__ B2, int NB1, int ldb,
              const float* __restrict__ bias1, const float* __restrict__ bias2,
              const float* __restrict__ anchors,
              float* __restrict__ C, int M, int N, int K, int ldc,
              size_t sA, size_t sB, size_t sC) {
    __shared__ float As[2][GBK][SAS];
    __shared__ float Bs[2][GBK][SBS];

    A1 += sA * blockIdx.z;
    A2 += sA * blockIdx.z;
    B1 += sB * blockIdx.z;
    C  += sC * blockIdx.z;
    int bm = blockIdx.y * GBM;
    int bn = blockIdx.x * GBN;

    int tid  = threadIdx.x;
    int wid  = tid >> 5, lane = tid & 31;
    int wm   = wid & 3;        // 4 warps along M, 32 rows each
    int wn   = wid >> 2;       // 2 warps along N, 64 cols each
    int lr   = lane >> 2;      // groupID
    int lc   = lane & 3;       // threadID-in-group

    float acc[2][8][4];
#pragma unroll
    for (int mi = 0; mi < 2; ++mi)
#pragma unroll
        for (int ni = 0; ni < 8; ++ni)
#pragma unroll
            for (int r = 0; r < 4; ++r) acc[mi][ni][r] = 0.0f;

    int nstages = (K + GBK - 1) / GBK;

    // ---- prologue: stage 0 into buffer 0 ----
#pragma unroll
    for (int q = 0; q < 2; ++q) {
        int linear = tid + 256 * q;
        int r = linear >> 2, c4 = linear & 3;
        float4 va = ldA(A1, A2, KA1, lda, M, K, bm, linear, 0);
        As[0][c4 * 4 + 0][r] = va.x;
        As[0][c4 * 4 + 1][r] = va.y;
        As[0][c4 * 4 + 2][r] = va.z;
        As[0][c4 * 4 + 3][r] = va.w;
        float4 vb = ldB(B1, B2, NB1, ldb, N, K, bn, linear, 0);
        Bs[0][c4 * 4 + 0][r] = vb.x;
        Bs[0][c4 * 4 + 1][r] = vb.y;
        Bs[0][c4 * 4 + 2][r] = vb.z;
        Bs[0][c4 * 4 + 3][r] = vb.w;
    }
    __syncthreads();

    for (int i = 0; i < nstages; ++i) {
        int cur = i & 1;
        // ---- prefetch next stage into registers ----
        float4 pA[2], pB[2];
        if (i + 1 < nstages) {
#pragma unroll
            for (int q = 0; q < 2; ++q) {
                int linear = tid + 256 * q;
                pA[q] = ldA(A1, A2, KA1, lda, M, K, bm, linear, (i + 1) * GBK);
                pB[q] = ldB(B1, B2, NB1, ldb, N, K, bn, linear, (i + 1) * GBK);
            }
        }
        // ---- compute current stage ----
#pragma unroll
        for (int kk = 0; kk < GBK; kk += 8) {
            uint32_t af[2][4], bf[8][2];
#pragma unroll
            for (int mi = 0; mi < 2; ++mi) {
                int m = wm * 32 + mi * 16 + lr;
                af[mi][0] = f2tf(As[cur][kk + lc    ][m]);
                af[mi][1] = f2tf(As[cur][kk + lc    ][m + 8]);
                af[mi][2] = f2tf(As[cur][kk + lc + 4][m]);
                af[mi][3] = f2tf(As[cur][kk + lc + 4][m + 8]);
            }
#pragma unroll
            for (int ni = 0; ni < 8; ++ni) {
                int n = wn * 64 + ni * 8 + lr;
                bf[ni][0] = f2tf(Bs[cur][kk + lc    ][n]);
                bf[ni][1] = f2tf(Bs[cur][kk + lc + 4][n]);
            }
#pragma unroll
            for (int mi = 0; mi < 2; ++mi)
#pragma unroll
                for (int ni = 0; ni < 8; ++ni)
                    mma_tf32(acc[mi][ni], af[mi], bf[ni]);
        }
        // ---- commit prefetch into other buffer ----
        if (i + 1 < nstages) {
            int nxt = cur ^ 1;
            __syncthreads();
#pragma unroll
            for (int q = 0; q < 2; ++q) {
                int linear = tid + 256 * q;
                int r = linear >> 2, c4 = linear & 3;
                As[nxt][c4 * 4 + 0][r] = pA[q].x;
                As[nxt][c4 * 4 + 1][r] = pA[q].y;
                As[nxt][c4 * 4 + 2][r] = pA[q].z;
                As[nxt][c4 * 4 + 3][r] = pA[q].w;
                Bs[nxt][c4 * 4 + 0][r] = pB[q].x;
                Bs[nxt][c4 * 4 + 1][r] = pB[q].y;
                Bs[nxt][c4 * 4 + 2][r] = pB[q].z;
                Bs[nxt][c4 * 4 + 3][r] = pB[q].w;
            }
            __syncthreads();
        }
    }

    // ---- epilogue ----
#pragma unroll
    for (int mi = 0; mi < 2; ++mi) {
#pragma unroll
        for (int ni = 0; ni < 8; ++ni) {
            float* d = acc[mi][ni];
            int mb = bm + wm * 32 + mi * 16 + lr;
            int nb = bn + wn * 64 + ni * 8 + lc * 2;
            epi_store<EPI>(C, ldc, M, N, bias1, bias2, anchors, mb,     nb,     d[0]);
            epi_store<EPI>(C, ldc, M, N, bias1, bias2, anchors, mb,     nb + 1, d[1]);
            epi_store<EPI>(C, ldc, M, N, bias1, bias2, anchors, mb + 8, nb,     d[2]);
            epi_store<EPI>(C, ldc, M, N, bias1, bias2, anchors, mb + 8, nb + 1, d[3]);
        }
    }
}

// =============================== softmax ====================================
__global__ __launch_bounds__(256)
void softmax_kernel(const float* __restrict__ scores, float* __restrict__ attn_out) {
    __shared__ float red[256];
    int m = blockIdx.x;
    int i = m % Nn;
    int t = threadIdx.x;
    const float* row = scores + (size_t)m * 1000;

    float v[4];
    float mx = -INFINITY;
#pragma unroll
    for (int r = 0; r < 4; ++r) {
        int j = t + r * 256;
        v[r] = (j < Nn - 1) ? row[j] : -INFINITY;
        mx = fmaxf(mx, v[r]);
    }
    red[t] = mx;
    __syncthreads();
    for (int s = 128; s > 0; s >>= 1) {
        if (t < s) red[t] = fmaxf(red[t], red[t + s]);
        __syncthreads();
    }
    mx = red[0];
    __syncthreads();

    float sum = 0.0f;
#pragma unroll
    for (int r = 0; r < 4; ++r) {
        int j = t + r * 256;
        v[r] = (j < Nn - 1) ? __expf(v[r] - mx) : 0.0f;
        sum += v[r];
    }
    red[t] = sum;
    __syncthreads();
    for (int s = 128; s > 0; s >>= 1) {
        if (t < s) red[t] += red[t + s];
        __syncthreads();
    }
    float inv = 1.0f / red[0];

    float* out = attn_out + (size_t)m * Nn;
#pragma unroll
    for (int r = 0; r < 4; ++r) {
        int j = t + r * 256;
        if (j < Nn - 1) {
            int pos = j + (j >= i);
            out[pos] = v[r] * inv;
        }
    }
    if (t == 0) out[i] = 0.0f;
}

// ============================ anchors passthrough ===========================
__global__ void anchor_kernel(const float* __restrict__ anchors, float* __restrict__ out) {
    int idx = blockIdx.x * blockDim.x + threadIdx.x;
    if (idx >= Bb * Nn * 3) return;
    int m = idx / 3, t = idx % 3;
    out[(size_t)m * NCOLS + 2 + t] = anchors[(size_t)(m % Nn) * NCOLS + 2 + t];
}

// ===========================================================================
extern "C" void kernel_launch(void* const* d_in, const int* in_sizes, int n_in,
                              void* d_out, int out_size) {
    const float*    x       = (const float*)d_in[0];
    const float*    conv_w  = (const float*)d_in[1];
    const float*    conv_b  = (const float*)d_in[2];
    const int*      cut_xs  = (const int*)d_in[3];
    const unsigned* invalid = (const unsigned*)d_in[4];
    const float*    anchors = (const float*)d_in[5];
    const float*    attn_w  = (const float*)d_in[6];
    const float*    attn_b  = (const float*)d_in[7];
    const float*    cls_w   = (const float*)d_in[8];
    const float*    cls_b   = (const float*)d_in[9];
    const float*    reg_w   = (const float*)d_in[10];
    const float*    reg_b   = (const float*)d_in[11];

    float* out       = (float*)d_out;
    float* out_reg   = out;
    float* out_attn  = out + OUT_REG_ELEMS;
    float* out_feats = out_attn + OUT_ATTN_ELEMS;

    float *baf, *bafT, *att, *scores;
    cudaGetSymbolAddress((void**)&baf, g_baf);
    cudaGetSymbolAddress((void**)&bafT, g_bafT);
    cudaGetSymbolAddress((void**)&att, g_att);
    cudaGetSymbolAddress((void**)&scores, g_scores);

    // 1) 1x1 conv -> feats (in d_out)
    conv_kernel<<<480, 256>>>(x, conv_w, conv_b, out_feats);

    // 2) ROI gather -> baf
    gather_kernel<<<160000, 256>>>(out_feats, cut_xs, invalid, baf);

    // 3) bafT[b][d][n] = baf[b][n][d]
    transpose_kernel<<<dim3(Dd / 32, 32, Bb), dim3(32, 8)>>>(baf, bafT);

    // 4) scores = baf @ attn_w^T + attn_b   (M=16000 N=999 K=2560)
    mma_gemm<0><<<dim3(8, 125, 1), 256>>>(
        baf, baf, Dd, Dd, attn_w, attn_w, Nn - 1, Dd,
        attn_b, nullptr, nullptr,
        scores, Bb * Nn, Nn - 1, Dd, 1000, 0, 0, 0);

    // 5) softmax + diagonal-zero scatter -> attn_mat (in d_out)
    softmax_kernel<<<Bb * Nn, 256>>>(scores, out_attn);

    // 6) att = attn_mat @ bafT^T (per batch: M=1000 N=2560 K=1000)
    mma_gemm<1><<<dim3(20, 8, Bb), 256>>>(
        out_attn, out_attn, Nn, Nn, bafT, bafT, Dd, Nn,
        nullptr, nullptr, nullptr,
        att, Nn, Dd, Nn, Dd,
        (size_t)Nn * Nn, (size_t)Nn * Dd, (size_t)Nn * Dd);

    // 7) fused reg+cls GEMM over concat A=[att|baf] (M=16000 N=290 K=5120)
    mma_gemm<2><<<dim3(3, 125, 1), 256>>>(
        att, baf, Dd, Dd, reg_w, cls_w, 3 * Ss, 2 * Dd,
        reg_b, cls_b, anchors,
        out_reg, Bb * Nn, 3 * Ss + 2, 2 * Dd, NCOLS, 0, 0, 0);

    // 8) anchors[:, 2:5] passthrough
    anchor_kernel<<<(Bb * Nn * 3 + 255) / 256, 256>>>(anchors, out_reg);
}

// round 5
// speedup vs baseline: 2.3265x; 1.0638x over previous
#include <cuda_runtime.h>
#include <math.h>
#include <stdint.h>

// Problem constants
#define Bb   16
#define CIN  64
#define Hh   160
#define Ww   192
#define Nn   1000
#define AFC  16
#define Ss   96
#define Dd   2560          // AFC * H
#define HW   30720         // H * W
#define NCOLS 293

#define OUT_REG_ELEMS  ((size_t)Bb * Nn * NCOLS)
#define OUT_ATTN_ELEMS ((size_t)Bb * Nn * Nn)

// ---------------- scratch ----------------
__device__ float g_baf[(size_t)Bb * Nn * Dd];      // 164 MB
__device__ float g_bafT[(size_t)Bb * Nn * Dd];     // 164 MB ([D][N] per batch)
__device__ float g_att[(size_t)Bb * Nn * Dd];      // 164 MB
__device__ float g_scores[(size_t)Bb * Nn * 1000]; // 64 MB

// =============================== conv ======================================
__global__ __launch_bounds__(256)
void conv_kernel(const float* __restrict__ x, const float* __restrict__ w,
                 const float* __restrict__ bias, float* __restrict__ feats) {
    __shared__ float ws[AFC * CIN];
    __shared__ float bs[AFC];
    int tid = threadIdx.x;
    for (int t = tid; t < AFC * CIN; t += 256) ws[t] = w[t];
    if (tid < AFC) bs[tid] = bias[tid];
    __syncthreads();

    unsigned idx = blockIdx.x * 256u + tid;
    if (idx >= (unsigned)(Bb * (HW / 4))) return;
    int b = idx / (HW / 4);
    int q = idx % (HW / 4);
    size_t hw = (size_t)q * 4;

    const float* xp = x + (size_t)b * CIN * HW + hw;
    float4 acc[AFC];
#pragma unroll
    for (int o = 0; o < AFC; ++o) {
        float bv = bs[o];
        acc[o] = make_float4(bv, bv, bv, bv);
    }
#pragma unroll 4
    for (int c = 0; c < CIN; ++c) {
        float4 xv = *(const float4*)(xp + (size_t)c * HW);
#pragma unroll
        for (int o = 0; o < AFC; ++o) {
            float wv = ws[o * CIN + c];
            acc[o].x += xv.x * wv; acc[o].y += xv.y * wv;
            acc[o].z += xv.z * wv; acc[o].w += xv.w * wv;
        }
    }
    float* fp = feats + (size_t)b * AFC * HW + hw;
#pragma unroll
    for (int o = 0; o < AFC; ++o)
        *(float4*)(fp + (size_t)o * HW) = acc[o];
}

// =============================== gather ====================================
__global__ __launch_bounds__(256)
void gather_kernel(const float* __restrict__ feats, const int* __restrict__ cut_xs,
                   const unsigned* __restrict__ invalid, float* __restrict__ baf) {
    unsigned idx = blockIdx.x * 256u + threadIdx.x;   // 40,960,000 exactly
    int h = idx % Hh;
    unsigned r = idx / Hh;
    int a = r % AFC; r /= AFC;
    int n = r % Nn;
    int b = r / Nn;
    int xi = cut_xs[n * Hh + h];
    float v = 0.0f;
    if (invalid[n * Hh + h] == 0u)
        v = feats[(((size_t)b * AFC + a) * Hh + h) * Ww + xi];
    baf[(size_t)idx] = v;
}

// ============================ transpose baf -> bafT =========================
__global__ __launch_bounds__(256)
void transpose_kernel(const float* __restrict__ src, float* __restrict__ dst) {
    __shared__ float tile[32][33];
    int b = blockIdx.z;
    int n0 = blockIdx.y * 32, d0 = blockIdx.x * 32;
    const float* s = src + (size_t)b * Nn * Dd;
    float* dt = dst + (size_t)b * Nn * Dd;
    int tx = threadIdx.x, ty = threadIdx.y;  // 32 x 8
#pragma unroll
    for (int r = ty; r < 32; r += 8) {
        int n = n0 + r;
        tile[r][tx] = (n < Nn) ? s[(size_t)n * Dd + d0 + tx] : 0.0f;
    }
    __syncthreads();
#pragma unroll
    for (int r = ty; r < 32; r += 8) {
        int n = n0 + tx;
        if (n < Nn) dt[(size_t)(d0 + r) * Nn + n] = tile[tx][r];
    }
}

// ====================== tf32 warp-MMA GEMM (TN) =============================
// C[M,N] = A[M,K] * B[N,K]^T  via mma.sync.m16n8k8.tf32
// SMEM holds PRE-CONVERTED tf32 bit patterns (uint32): inner loop = LDS + HMMA.
#define GBM 128
#define GBN 128
#define GBK 16
#define SAS (GBM + 8)
#define SBS (GBN + 8)

__device__ __forceinline__ uint32_t f2tf(float f) {
    uint32_t u;
    asm("cvt.rna.tf32.f32 %0, %1;" : "=r"(u) : "f"(f));
    return u;
}
__device__ __forceinline__ void mma_tf32(float* d, const uint32_t* a, const uint32_t* b) {
    asm volatile(
        "mma.sync.aligned.m16n8k8.row.col.f32.tf32.tf32.f32 "
        "{%0,%1,%2,%3}, {%4,%5,%6,%7}, {%8,%9}, {%0,%1,%2,%3};"
        : "+f"(d[0]), "+f"(d[1]), "+f"(d[2]), "+f"(d[3])
        : "r"(a[0]), "r"(a[1]), "r"(a[2]), "r"(a[3]), "r"(b[0]), "r"(b[1]));
}

__device__ __forceinline__ float4 ldA(const float* A1, const float* A2, int KA1, int lda,
                                      int M, int K, int bm, int linear, int k0) {
    int r = linear >> 2, c4 = linear & 3;
    int gr = bm + r, k = k0 + c4 * 4;
    float4 v = make_float4(0.f, 0.f, 0.f, 0.f);
    if (gr < M && k < K) {
        const float* s = (k < KA1) ? A1 + (size_t)gr * lda + k
                                   : A2 + (size_t)gr * lda + (k - KA1);
        v = *(const float4*)s;
    }
    return v;
}
__device__ __forceinline__ float4 ldB(const float* B1, const float* B2, int NB1, int ldb,
                                      int N, int K, int bn, int linear, int k0) {
    int r = linear >> 2, c4 = linear & 3;
    int gn = bn + r, k = k0 + c4 * 4;
    float4 v = make_float4(0.f, 0.f, 0.f, 0.f);
    if (gn < N && k < K) {
        const float* s = (gn < NB1) ? B1 + (size_t)gn * ldb + k
                                    : B2 + (size_t)(gn - NB1) * ldb + k;
        v = *(const float4*)s;
    }
    return v;
}

template<int EPI>
__device__ __forceinline__ void epi_store(float* __restrict__ C, int ldc, int M, int N,
                                          const float* __restrict__ bias1,
                                          const float* __restrict__ bias2,
                                          const float* __restrict__ anchors,
                                          int m, int n, float v) {
    if (m >= M || n >= N) return;
    if (EPI == 0) {
        C[(size_t)m * ldc + n] = v + bias1[n];
    } else if (EPI == 1) {
        C[(size_t)m * ldc + n] = v;
    } else {
        int nidx = m % Nn;
        if (n < 288) {
            v += bias1[n];
            if (n >= 192) v = 1.0f / (1.0f + expf(-v));
            v += anchors[(size_t)nidx * NCOLS + 5 + n];
            C[(size_t)m * ldc + 5 + n] = v;
        } else {
            C[(size_t)m * ldc + (n - 288)] = v + bias2[n - 288];
        }
    }
}

template<int EPI>
__global__ __launch_bounds__(256)
void mma_gemm(const float* __restrict__ A1, const float* __restrict__ A2, int KA1, int lda,
              const float* __restrict__ B1, const float* __restrict__ B2, int NB1, int ldb,
              const float* __restrict__ bias1, const float* __restrict__ bias2,
              const float* __restrict__ anchors,
              float* __restrict__ C, int M, int N, int K, int ldc,
              size_t sA, size_t sB, size_t sC) {
    __shared__ uint32_t As[2][GBK][SAS];
    __shared__ uint32_t Bs[2][GBK][SBS];

    A1 += sA * blockIdx.z;
    A2 += sA * blockIdx.z;
    B1 += sB * blockIdx.z;
    C  += sC * blockIdx.z;
    int bm = blockIdx.y * GBM;
    int bn = blockIdx.x * GBN;

    int tid  = threadIdx.x;
    int wid  = tid >> 5, lane = tid & 31;
    int wm   = wid & 3;        // 4 warps along M, 32 rows each
    int wn   = wid >> 2;       // 2 warps along N, 64 cols each
    int lr   = lane >> 2;      // groupID
    int lc   = lane & 3;       // threadID-in-group

    float acc[2][8][4];
#pragma unroll
    for (int mi = 0; mi < 2; ++mi)
#pragma unroll
        for (int ni = 0; ni < 8; ++ni)
#pragma unroll
            for (int r = 0; r < 4; ++r) acc[mi][ni][r] = 0.0f;

    int nstages = (K + GBK - 1) / GBK;

    // ---- prologue: stage 0 into buffer 0 (convert to tf32 at store) ----
#pragma unroll
    for (int q = 0; q < 2; ++q) {
        int linear = tid + 256 * q;
        int r = linear >> 2, c4 = linear & 3;
        float4 va = ldA(A1, A2, KA1, lda, M, K, bm, linear, 0);
        As[0][c4 * 4 + 0][r] = f2tf(va.x);
        As[0][c4 * 4 + 1][r] = f2tf(va.y);
        As[0][c4 * 4 + 2][r] = f2tf(va.z);
        As[0][c4 * 4 + 3][r] = f2tf(va.w);
        float4 vb = ldB(B1, B2, NB1, ldb, N, K, bn, linear, 0);
        Bs[0][c4 * 4 + 0][r] = f2tf(vb.x);
        Bs[0][c4 * 4 + 1][r] = f2tf(vb.y);
        Bs[0][c4 * 4 + 2][r] = f2tf(vb.z);
        Bs[0][c4 * 4 + 3][r] = f2tf(vb.w);
    }
    __syncthreads();

    for (int i = 0; i < nstages; ++i) {
        int cur = i & 1;
        // ---- prefetch next stage into registers ----
        float4 pA[2], pB[2];
        if (i + 1 < nstages) {
#pragma unroll
            for (int q = 0; q < 2; ++q) {
                int linear = tid + 256 * q;
                pA[q] = ldA(A1, A2, KA1, lda, M, K, bm, linear, (i + 1) * GBK);
                pB[q] = ldB(B1, B2, NB1, ldb, N, K, bn, linear, (i + 1) * GBK);
            }
        }
        // ---- compute current stage: pure LDS + HMMA ----
#pragma unroll
        for (int kk = 0; kk < GBK; kk += 8) {
            uint32_t af[2][4], bf[8][2];
#pragma unroll
            for (int mi = 0; mi < 2; ++mi) {
                int m = wm * 32 + mi * 16 + lr;
                af[mi][0] = As[cur][kk + lc    ][m];
                af[mi][1] = As[cur][kk + lc    ][m + 8];
                af[mi][2] = As[cur][kk + lc + 4][m];
                af[mi][3] = As[cur][kk + lc + 4][m + 8];
            }
#pragma unroll
            for (int ni = 0; ni < 8; ++ni) {
                int n = wn * 64 + ni * 8 + lr;
                bf[ni][0] = Bs[cur][kk + lc    ][n];
                bf[ni][1] = Bs[cur][kk + lc + 4][n];
            }
#pragma unroll
            for (int mi = 0; mi < 2; ++mi)
#pragma unroll
                for (int ni = 0; ni < 8; ++ni)
                    mma_tf32(acc[mi][ni], af[mi], bf[ni]);
        }
        // ---- commit prefetch into other buffer (convert at store) ----
        if (i + 1 < nstages) {
            int nxt = cur ^ 1;
            __syncthreads();
#pragma unroll
            for (int q = 0; q < 2; ++q) {
                int linear = tid + 256 * q;
                int r = linear >> 2, c4 = linear & 3;
                As[nxt][c4 * 4 + 0][r] = f2tf(pA[q].x);
                As[nxt][c4 * 4 + 1][r] = f2tf(pA[q].y);
                As[nxt][c4 * 4 + 2][r] = f2tf(pA[q].z);
                As[nxt][c4 * 4 + 3][r] = f2tf(pA[q].w);
                Bs[nxt][c4 * 4 + 0][r] = f2tf(pB[q].x);
                Bs[nxt][c4 * 4 + 1][r] = f2tf(pB[q].y);
                Bs[nxt][c4 * 4 + 2][r] = f2tf(pB[q].z);
                Bs[nxt][c4 * 4 + 3][r] = f2tf(pB[q].w);
            }
            __syncthreads();
        }
    }

    // ---- epilogue ----
#pragma unroll
    for (int mi = 0; mi < 2; ++mi) {
#pragma unroll
        for (int ni = 0; ni < 8; ++ni) {
            float* d = acc[mi][ni];
            int mb = bm + wm * 32 + mi * 16 + lr;
            int nb = bn + wn * 64 + ni * 8 + lc * 2;
            epi_store<EPI>(C, ldc, M, N, bias1, bias2, anchors, mb,     nb,     d[0]);
            epi_store<EPI>(C, ldc, M, N, bias1, bias2, anchors, mb,     nb + 1, d[1]);
            epi_store<EPI>(C, ldc, M, N, bias1, bias2, anchors, mb + 8, nb,     d[2]);
            epi_store<EPI>(C, ldc, M, N, bias1, bias2, anchors, mb + 8, nb + 1, d[3]);
        }
    }
}

// =============================== softmax ====================================
__global__ __launch_bounds__(256)
void softmax_kernel(const float* __restrict__ scores, float* __restrict__ attn_out) {
    __shared__ float red[256];
    int m = blockIdx.x;
    int i = m % Nn;
    int t = threadIdx.x;
    const float* row = scores + (size_t)m * 1000;

    float v[4];
    float mx = -INFINITY;
#pragma unroll
    for (int r = 0; r < 4; ++r) {
        int j = t + r * 256;
        v[r] = (j < Nn - 1) ? row[j] : -INFINITY;
        mx = fmaxf(mx, v[r]);
    }
    red[t] = mx;
    __syncthreads();
    for (int s = 128; s > 0; s >>= 1) {
        if (t < s) red[t] = fmaxf(red[t], red[t + s]);
        __syncthreads();
    }
    mx = red[0];
    __syncthreads();

    float sum = 0.0f;
#pragma unroll
    for (int r = 0; r < 4; ++r) {
        int j = t + r * 256;
        v[r] = (j < Nn - 1) ? __expf(v[r] - mx) : 0.0f;
        sum += v[r];
    }
    red[t] = sum;
    __syncthreads();
    for (int s = 128; s > 0; s >>= 1) {
        if (t < s) red[t] += red[t + s];
        __syncthreads();
    }
    float inv = 1.0f / red[0];

    float* out = attn_out + (size_t)m * Nn;
#pragma unroll
    for (int r = 0; r < 4; ++r) {
        int j = t + r * 256;
        if (j < Nn - 1) {
            int pos = j + (j >= i);
            out[pos] = v[r] * inv;
        }
    }
    if (t == 0) out[i] = 0.0f;
}

// ============================ anchors passthrough ===========================
__global__ void anchor_kernel(const float* __restrict__ anchors, float* __restrict__ out) {
    int idx = blockIdx.x * blockDim.x + threadIdx.x;
    if (idx >= Bb * Nn * 3) return;
    int m = idx / 3, t = idx % 3;
    out[(size_t)m * NCOLS + 2 + t] = anchors[(size_t)(m % Nn) * NCOLS + 2 + t];
}

// ===========================================================================
extern "C" void kernel_launch(void* const* d_in, const int* in_sizes, int n_in,
                              void* d_out, int out_size) {
    const float*    x       = (const float*)d_in[0];
    const float*    conv_w  = (const float*)d_in[1];
    const float*    conv_b  = (const float*)d_in[2];
    const int*      cut_xs  = (const int*)d_in[3];
    const unsigned* invalid = (const unsigned*)d_in[4];
    const float*    anchors = (const float*)d_in[5];
    const float*    attn_w  = (const float*)d_in[6];
    const float*    attn_b  = (const float*)d_in[7];
    const float*    cls_w   = (const float*)d_in[8];
    const float*    cls_b   = (const float*)d_in[9];
    const float*    reg_w   = (const float*)d_in[10];
    const float*    reg_b   = (const float*)d_in[11];

    float* out       = (float*)d_out;
    float* out_reg   = out;
    float* out_attn  = out + OUT_REG_ELEMS;
    float* out_feats = out_attn + OUT_ATTN_ELEMS;

    float *baf, *bafT, *att, *scores;
    cudaGetSymbolAddress((void**)&baf, g_baf);
    cudaGetSymbolAddress((void**)&bafT, g_bafT);
    cudaGetSymbolAddress((void**)&att, g_att);
    cudaGetSymbolAddress((void**)&scores, g_scores);

    // 1) 1x1 conv -> feats (in d_out)
    conv_kernel<<<480, 256>>>(x, conv_w, conv_b, out_feats);

    // 2) ROI gather -> baf
    gather_kernel<<<160000, 256>>>(out_feats, cut_xs, invalid, baf);

    // 3) bafT[b][d][n] = baf[b][n][d]
    transpose_kernel<<<dim3(Dd / 32, 32, Bb), dim3(32, 8)>>>(baf, bafT);

    // 4) scores = baf @ attn_w^T + attn_b   (M=16000 N=999 K=2560)
    mma_gemm<0><<<dim3(8, 125, 1), 256>>>(
        baf, baf, Dd, Dd, attn_w, attn_w, Nn - 1, Dd,
        attn_b, nullptr, nullptr,
        scores, Bb * Nn, Nn - 1, Dd, 1000, 0, 0, 0);

    // 5) softmax + diagonal-zero scatter -> attn_mat (in d_out)
    softmax_kernel<<<Bb * Nn, 256>>>(scores, out_attn);

    // 6) att = attn_mat @ bafT^T (per batch: M=1000 N=2560 K=1000)
    mma_gemm<1><<<dim3(20, 8, Bb), 256>>>(
        out_attn, out_attn, Nn, Nn, bafT, bafT, Dd, Nn,
        nullptr, nullptr, nullptr,
        att, Nn, Dd, Nn, Dd,
        (size_t)Nn * Nn, (size_t)Nn * Dd, (size_t)Nn * Dd);

    // 7) fused reg+cls GEMM over concat A=[att|baf] (M=16000 N=290 K=5120)
    mma_gemm<2><<<dim3(3, 125, 1), 256>>>(
        att, baf, Dd, Dd, reg_w, cls_w, 3 * Ss, 2 * Dd,
        reg_b, cls_b, anchors,
        out_reg, Bb * Nn, 3 * Ss + 2, 2 * Dd, NCOLS, 0, 0, 0);

    // 8) anchors[:, 2:5] passthrough
    anchor_kernel<<<(Bb * Nn * 3 + 255) / 256, 256>>>(anchors, out_reg);
}